// round 3
// baseline (speedup 1.0000x reference)
#include <cuda_runtime.h>
#include <math.h>

#define NROWS 65536
#define KDIM  512
#define A3    64
#define CWIN  16
#define DTOW  8
#define PLEN  96

typedef unsigned long long u64;

// ---------------- scratch (device globals; no allocations allowed) ----------
__device__ float g_t   [(size_t)NROWS * A3];            // 16 MB
__device__ float g_rep [(size_t)NROWS * A3];            // 16 MB (row-major)
__device__ float g_repT[(size_t)A3 * NROWS];            // 16 MB (k-major)
__device__ float g_h   [(size_t)DTOW * NROWS * A3];     // 128 MB
__device__ float g_y   [(size_t)DTOW * NROWS * PLEN];   // 192 MB
__device__ float g_sum[DTOW * A3];
__device__ float g_sq [DTOW * A3];
__device__ float g_scale[DTOW * A3];
__device__ float g_shift[DTOW * A3];

// ---------------- packed f32x2 helpers ---------------------------------------
__device__ __forceinline__ u64 ffma2(u64 a, u64 b, u64 c) {
    u64 d;
    asm("fma.rn.f32x2 %0, %1, %2, %3;" : "=l"(d) : "l"(a), "l"(b), "l"(c));
    return d;
}
__device__ __forceinline__ u64 pack2(float lo, float hi) {
    u64 r; asm("mov.b64 %0, {%1, %2};" : "=l"(r) : "f"(lo), "f"(hi)); return r;
}
__device__ __forceinline__ float2 unpack2(u64 v) {
    float2 f; asm("mov.b64 {%0, %1}, %2;" : "=f"(f.x), "=f"(f.y) : "l"(v)); return f;
}

// ---------------- K1: t = normalize(x @ shuzhihua) ---------------------------
// 128x64 tile / block, 256 threads (16x16). FFMA2: 4 row-pairs x 4 cols.
__global__ void __launch_bounds__(256) k1_gemm_norm(const float* __restrict__ x,
                                                    const float* __restrict__ w) {
    __shared__ float As_T[32][132];        // k-major A (transposed in loader)
    __shared__ u64   Bdup[32][64];         // B with both halves duplicated
    __shared__ float rnorm[128];
    const int tid = threadIdx.x;
    const int tx = tid & 15, ty = tid >> 4;
    const int r0 = blockIdx.x * 128;

    u64 acc[4][4];
#pragma unroll
    for (int rp = 0; rp < 4; rp++)
#pragma unroll
        for (int cc = 0; cc < 4; cc++) acc[rp][cc] = pack2(0.f, 0.f);

    for (int k0 = 0; k0 < KDIM; k0 += 32) {
        // A chunk (transpose): 128 rows x 32 k
#pragma unroll
        for (int i = 0; i < 4; i++) {
            int idx = tid + i * 256;
            int row = idx >> 3, kq = idx & 7;
            float4 v = *(const float4*)&x[(size_t)(r0 + row) * KDIM + k0 + kq * 4];
            As_T[kq * 4 + 0][row] = v.x; As_T[kq * 4 + 1][row] = v.y;
            As_T[kq * 4 + 2][row] = v.z; As_T[kq * 4 + 3][row] = v.w;
        }
        // B chunk duplicated: 32 x 64
#pragma unroll
        for (int i = 0; i < 2; i++) {
            int idx = tid + i * 256;
            int kk = idx >> 4, cq = idx & 15;
            float4 v = *(const float4*)&w[(size_t)(k0 + kk) * A3 + cq * 4];
            Bdup[kk][cq * 4 + 0] = pack2(v.x, v.x);
            Bdup[kk][cq * 4 + 1] = pack2(v.y, v.y);
            Bdup[kk][cq * 4 + 2] = pack2(v.z, v.z);
            Bdup[kk][cq * 4 + 3] = pack2(v.w, v.w);
        }
        __syncthreads();
#pragma unroll 8
        for (int k = 0; k < 32; k++) {
            const ulonglong2* ap = (const ulonglong2*)&As_T[k][ty * 8];
            ulonglong2 aA = ap[0], aB = ap[1];
            u64 ar[4] = {aA.x, aA.y, aB.x, aB.y};
            u64 b[4];
#pragma unroll
            for (int cc = 0; cc < 4; cc++) b[cc] = Bdup[k][tx * 4 + cc];
#pragma unroll
            for (int rp = 0; rp < 4; rp++)
#pragma unroll
                for (int cc = 0; cc < 4; cc++)
                    acc[rp][cc] = ffma2(ar[rp], b[cc], acc[rp][cc]);
        }
        __syncthreads();
    }
    // unpack to per-row values
    float v[8][4];
#pragma unroll
    for (int rp = 0; rp < 4; rp++)
#pragma unroll
        for (int cc = 0; cc < 4; cc++) {
            float2 f = unpack2(acc[rp][cc]);
            v[2 * rp][cc] = f.x; v[2 * rp + 1][cc] = f.y;
        }
    if (tid < 128) rnorm[tid] = 0.f;
    __syncthreads();
#pragma unroll
    for (int rr = 0; rr < 8; rr++) {
        float p = v[rr][0] * v[rr][0] + v[rr][1] * v[rr][1]
                + v[rr][2] * v[rr][2] + v[rr][3] * v[rr][3];
        atomicAdd(&rnorm[ty * 8 + rr], p);
    }
    __syncthreads();
#pragma unroll
    for (int rr = 0; rr < 8; rr++) {
        float s = 1.f / fmaxf(sqrtf(rnorm[ty * 8 + rr]), 1e-12f);
        *(float4*)&g_t[(size_t)(r0 + ty * 8 + rr) * A3 + tx * 4] =
            make_float4(v[rr][0] * s, v[rr][1] * s, v[rr][2] * s, v[rr][3] * s);
    }
}

// ---------------- K2: windowed FIR sum over C=16 rows ------------------------
__global__ void __launch_bounds__(256) k2_window(const float* __restrict__ lw,
                                                 const float* __restrict__ lb,
                                                 float* __restrict__ rep_out) {
    __shared__ float ts[143 * 64];
    __shared__ float lws[16 * 64];
    __shared__ float sb[64];
    const int tid = threadIdx.x;
    const int r0 = blockIdx.x * 128;
    const int base = (r0 >= 15) ? (r0 - 15) : 0;
    const int nrows = r0 + 128 - base;

    for (int i = tid; i < nrows * 16; i += 256)
        ((float4*)ts)[i] = *(const float4*)&g_t[(size_t)base * A3 + (size_t)i * 4];
    for (int i = tid; i < 256; i += 256)
        ((float4*)lws)[i] = ((const float4*)lw)[i];
    if (tid < 64) {
        float s = 0.f;
#pragma unroll
        for (int j = 0; j < 16; j++) s += lb[j * 64 + tid];
        sb[tid] = s;
    }
    __syncthreads();

    const int c = tid & 63;
    const int rg = tid >> 6;
    float lwr[16];
#pragma unroll
    for (int j = 0; j < 16; j++) lwr[j] = lws[j * 64 + c];
    const float sbc = sb[c];

    for (int rr = 0; rr < 32; rr++) {
        int i = r0 + rg * 32 + rr;
        float accv = sbc;
        if (i >= 15) {
            int off = i - 15 - base;
#pragma unroll
            for (int j = 0; j < 16; j++) accv += lwr[j] * ts[(off + j) * 64 + c];
        } else {
#pragma unroll
            for (int j = 0; j < 16; j++) {
                int s = (j < i) ? j : i;
                accv += lwr[j] * ts[s * 64 + c];
            }
        }
        g_rep[(size_t)i * A3 + c] = accv;
        if (rep_out) rep_out[(size_t)i * A3 + c] = accv;
    }
}

// ---------------- K2t: rep -> rep_T (k-major for k3) -------------------------
__global__ void __launch_bounds__(256) k2t_transpose() {
    __shared__ float tile[32][33];
    const int tx = threadIdx.x & 31, ty = threadIdx.x >> 5;  // 32x8
    const int r0 = blockIdx.x * 32;
    const int c0 = blockIdx.y * 32;
#pragma unroll
    for (int j = 0; j < 32; j += 8)
        tile[ty + j][tx] = g_rep[(size_t)(r0 + ty + j) * A3 + c0 + tx];
    __syncthreads();
#pragma unroll
    for (int j = 0; j < 32; j += 8)
        g_repT[(size_t)(c0 + ty + j) * NROWS + r0 + tx] = tile[tx][ty + j];
}

// ---------------- zero BN accumulators ---------------------------------------
__global__ void kz_zero() {
    int i = threadIdx.x;
    if (i < DTOW * A3) { g_sum[i] = 0.f; g_sq[i] = 0.f; }
}

// ---------------- K3: h[d] = rep @ W1[d] + b1[d]; BN stats -------------------
__global__ void __launch_bounds__(256) k3_tower1(const float* __restrict__ W1,
                                                 const float* __restrict__ b1) {
    __shared__ float As_T[32][132];
    __shared__ u64   Bdup[32][64];
    __shared__ float csum[64];
    __shared__ float csq[64];
    const int tid = threadIdx.x;
    const int tx = tid & 15, ty = tid >> 4;
    const int d = blockIdx.y;
    const int r0 = blockIdx.x * 128;
    if (tid < 64) { csum[tid] = 0.f; csq[tid] = 0.f; }

    u64 acc[4][4];
#pragma unroll
    for (int rp = 0; rp < 4; rp++)
#pragma unroll
        for (int cc = 0; cc < 4; cc++) acc[rp][cc] = pack2(0.f, 0.f);

    const float* W1d = W1 + (size_t)d * A3 * A3;
    for (int k0 = 0; k0 < A3; k0 += 32) {
        // A chunk from k-major rep_T: conflict-free, coalesced
#pragma unroll
        for (int i = 0; i < 4; i++) {
            int idx = tid + i * 256;
            int kk = idx >> 5, rq = idx & 31;
            *(float4*)&As_T[kk][rq * 4] =
                *(const float4*)&g_repT[(size_t)(k0 + kk) * NROWS + r0 + rq * 4];
        }
#pragma unroll
        for (int i = 0; i < 2; i++) {
            int idx = tid + i * 256;
            int kk = idx >> 4, cq = idx & 15;
            float4 v = *(const float4*)&W1d[(size_t)(k0 + kk) * A3 + cq * 4];
            Bdup[kk][cq * 4 + 0] = pack2(v.x, v.x);
            Bdup[kk][cq * 4 + 1] = pack2(v.y, v.y);
            Bdup[kk][cq * 4 + 2] = pack2(v.z, v.z);
            Bdup[kk][cq * 4 + 3] = pack2(v.w, v.w);
        }
        __syncthreads();
#pragma unroll 8
        for (int k = 0; k < 32; k++) {
            const ulonglong2* ap = (const ulonglong2*)&As_T[k][ty * 8];
            ulonglong2 aA = ap[0], aB = ap[1];
            u64 ar[4] = {aA.x, aA.y, aB.x, aB.y};
            u64 b[4];
#pragma unroll
            for (int cc = 0; cc < 4; cc++) b[cc] = Bdup[k][tx * 4 + cc];
#pragma unroll
            for (int rp = 0; rp < 4; rp++)
#pragma unroll
                for (int cc = 0; cc < 4; cc++)
                    acc[rp][cc] = ffma2(ar[rp], b[cc], acc[rp][cc]);
        }
        __syncthreads();
    }
    float v[8][4];
#pragma unroll
    for (int rp = 0; rp < 4; rp++)
#pragma unroll
        for (int cc = 0; cc < 4; cc++) {
            float2 f = unpack2(acc[rp][cc]);
            v[2 * rp][cc] = f.x; v[2 * rp + 1][cc] = f.y;
        }
    float4 bv = *(const float4*)&b1[d * A3 + tx * 4];
    float bb[4] = {bv.x, bv.y, bv.z, bv.w};
    float ls[4] = {0, 0, 0, 0}, lq[4] = {0, 0, 0, 0};
#pragma unroll
    for (int rr = 0; rr < 8; rr++) {
        float v0 = v[rr][0] + bb[0], v1 = v[rr][1] + bb[1];
        float v2 = v[rr][2] + bb[2], v3 = v[rr][3] + bb[3];
        *(float4*)&g_h[((size_t)d * NROWS + r0 + ty * 8 + rr) * A3 + tx * 4] =
            make_float4(v0, v1, v2, v3);
        ls[0] += v0; lq[0] += v0 * v0; ls[1] += v1; lq[1] += v1 * v1;
        ls[2] += v2; lq[2] += v2 * v2; ls[3] += v3; lq[3] += v3 * v3;
    }
#pragma unroll
    for (int cc = 0; cc < 4; cc++) {
        atomicAdd(&csum[tx * 4 + cc], ls[cc]);
        atomicAdd(&csq [tx * 4 + cc], lq[cc]);
    }
    __syncthreads();
    if (tid < 64) {
        atomicAdd(&g_sum[d * A3 + tid], csum[tid]);
        atomicAdd(&g_sq [d * A3 + tid], csq [tid]);
    }
}

// ---------------- K4: finalize BN -> fused scale/shift -----------------------
__global__ void k4_stats(const float* __restrict__ gamma,
                         const float* __restrict__ beta) {
    int i = threadIdx.x;
    if (i < DTOW * A3) {
        const float inv_n = 1.0f / (float)NROWS;
        float mean = g_sum[i] * inv_n;
        float var  = g_sq[i] * inv_n - mean * mean;
        float is   = rsqrtf(var + 1e-5f);
        float sc   = is * gamma[i];
        g_scale[i] = sc;
        g_shift[i] = beta[i] - mean * sc;
    }
}

// ---------------- K5: y[d] = elu(norm(h[d])) @ W2[d] + b2[d] -> g_y ----------
__global__ void __launch_bounds__(256) k5_tower2(const float* __restrict__ W2,
                                                 const float* __restrict__ b2) {
    __shared__ float hs_T[32][132];
    __shared__ u64   W2dup[32][96];
    const int tid = threadIdx.x;
    const int tx = tid & 15, ty = tid >> 4;
    const int d = blockIdx.y;
    const int r0 = blockIdx.x * 128;

    u64 acc[4][6];
#pragma unroll
    for (int rp = 0; rp < 4; rp++)
#pragma unroll
        for (int cc = 0; cc < 6; cc++) acc[rp][cc] = pack2(0.f, 0.f);

    const float* W2d = W2 + (size_t)d * A3 * PLEN;
    for (int k0 = 0; k0 < A3; k0 += 32) {
        // h chunk with fused affine + ELU, transposed to k-major
#pragma unroll
        for (int i = 0; i < 4; i++) {
            int idx = tid + i * 256;
            int row = idx >> 3, kq = idx & 7;
            float4 v  = *(const float4*)&g_h[((size_t)d * NROWS + r0 + row) * A3 + k0 + kq * 4];
            float4 sc = *(const float4*)&g_scale[d * A3 + k0 + kq * 4];
            float4 sh = *(const float4*)&g_shift[d * A3 + k0 + kq * 4];
            float t0 = v.x * sc.x + sh.x; t0 = t0 > 0.f ? t0 : expm1f(t0);
            float t1 = v.y * sc.y + sh.y; t1 = t1 > 0.f ? t1 : expm1f(t1);
            float t2 = v.z * sc.z + sh.z; t2 = t2 > 0.f ? t2 : expm1f(t2);
            float t3 = v.w * sc.w + sh.w; t3 = t3 > 0.f ? t3 : expm1f(t3);
            hs_T[kq * 4 + 0][row] = t0; hs_T[kq * 4 + 1][row] = t1;
            hs_T[kq * 4 + 2][row] = t2; hs_T[kq * 4 + 3][row] = t3;
        }
        // W2 chunk duplicated: 32 x 96
#pragma unroll
        for (int i = 0; i < 3; i++) {
            int idx = tid + i * 256;
            int kk = idx / 24, pq = idx % 24;
            float4 v = *(const float4*)&W2d[(size_t)(k0 + kk) * PLEN + pq * 4];
            W2dup[kk][pq * 4 + 0] = pack2(v.x, v.x);
            W2dup[kk][pq * 4 + 1] = pack2(v.y, v.y);
            W2dup[kk][pq * 4 + 2] = pack2(v.z, v.z);
            W2dup[kk][pq * 4 + 3] = pack2(v.w, v.w);
        }
        __syncthreads();
#pragma unroll 8
        for (int k = 0; k < 32; k++) {
            const ulonglong2* ap = (const ulonglong2*)&hs_T[k][ty * 8];
            ulonglong2 aA = ap[0], aB = ap[1];
            u64 ar[4] = {aA.x, aA.y, aB.x, aB.y};
            u64 b[6];
#pragma unroll
            for (int cc = 0; cc < 6; cc++) b[cc] = W2dup[k][tx * 6 + cc];
#pragma unroll
            for (int rp = 0; rp < 4; rp++)
#pragma unroll
                for (int cc = 0; cc < 6; cc++)
                    acc[rp][cc] = ffma2(ar[rp], b[cc], acc[rp][cc]);
        }
        __syncthreads();
    }
    float bb[6];
#pragma unroll
    for (int cc = 0; cc < 6; cc++) bb[cc] = b2[d * PLEN + tx * 6 + cc];
#pragma unroll
    for (int rp = 0; rp < 4; rp++) {
        size_t ro0 = ((size_t)d * NROWS + r0 + ty * 8 + 2 * rp) * PLEN;
        size_t ro1 = ro0 + PLEN;
#pragma unroll
        for (int cc = 0; cc < 6; cc++) {
            float2 f = unpack2(acc[rp][cc]);
            g_y[ro0 + tx * 6 + cc] = f.x + bb[cc];
            g_y[ro1 + tx * 6 + cc] = f.y + bb[cc];
        }
    }
}

// ---------------- K6: out[n, p*8+d] = g_y[d][n][p] ---------------------------
__global__ void __launch_bounds__(256) k6_interleave(float* __restrict__ out) {
    const size_t M = (size_t)NROWS * PLEN;
    size_t g = (size_t)blockIdx.x * 256 + threadIdx.x;
    float v[8];
#pragma unroll
    for (int d = 0; d < 8; d++) v[d] = g_y[(size_t)d * M + g];
    float4* o = (float4*)out;
    o[2 * g]     = make_float4(v[0], v[1], v[2], v[3]);
    o[2 * g + 1] = make_float4(v[4], v[5], v[6], v[7]);
}

// ---------------- launch ------------------------------------------------------
extern "C" void kernel_launch(void* const* d_in, const int* in_sizes, int n_in,
                              void* d_out, int out_size) {
    const float* x     = (const float*)d_in[0];
    const float* shu   = (const float*)d_in[1];
    const float* lw    = (const float*)d_in[2];
    const float* lb    = (const float*)d_in[3];
    const float* W1    = (const float*)d_in[4];
    const float* b1    = (const float*)d_in[5];
    const float* gamma = (const float*)d_in[6];
    const float* beta  = (const float*)d_in[7];
    const float* W2    = (const float*)d_in[8];
    const float* b2    = (const float*)d_in[9];
    float* out = (float*)d_out;

    float* rep_out = ((size_t)out_size >= (size_t)NROWS * (PLEN * DTOW + A3))
                         ? out + (size_t)NROWS * PLEN * DTOW
                         : nullptr;

    k1_gemm_norm<<<NROWS / 128, 256>>>(x, shu);
    k2_window<<<NROWS / 128, 256>>>(lw, lb, rep_out);
    k2t_transpose<<<dim3(NROWS / 32, A3 / 32), 256>>>();
    kz_zero<<<1, 512>>>();
    k3_tower1<<<dim3(NROWS / 128, DTOW), 256>>>(W1, b1);
    k4_stats<<<1, 512>>>(gamma, beta);
    k5_tower2<<<dim3(NROWS / 128, DTOW), 256>>>(W2, b2);
    k6_interleave<<<(NROWS * PLEN) / 256, 256>>>(out);
}

// round 4
// speedup vs baseline: 1.2120x; 1.2120x over previous
#include <cuda_runtime.h>
#include <math.h>

#define NROWS 65536
#define KDIM  512
#define A3    64
#define CWIN  16
#define DTOW  8
#define PLEN  96

// ---------------- scratch (device globals; no allocations allowed) ----------
__device__ float g_t   [(size_t)NROWS * A3];            // 16 MB
__device__ float g_rep [(size_t)NROWS * A3];            // 16 MB (row-major)
__device__ float g_repT[(size_t)A3 * NROWS];            // 16 MB (k-major)
__device__ float g_h   [(size_t)DTOW * NROWS * A3];     // 128 MB
__device__ float g_y   [(size_t)DTOW * NROWS * PLEN];   // 192 MB
__device__ float g_sum[DTOW * A3];
__device__ float g_sq [DTOW * A3];
__device__ float g_scale[DTOW * A3];
__device__ float g_shift[DTOW * A3];

// ---------------- K1: t = normalize(x @ shuzhihua) ---------------------------
// 128x64 tile / block, 256 threads (16x16), 8x4 micro-tile, BK=32.
// A tile stored k-major: per-k fragment = 2x LDS.128 (warp-broadcast).
__global__ void __launch_bounds__(256) k1_gemm_norm(const float* __restrict__ x,
                                                    const float* __restrict__ w) {
    __shared__ float As_T[32][132];   // [k][row], stride 132 (16B-aligned rows)
    __shared__ float Bs[32][64];
    __shared__ float rnorm[128];
    const int tid = threadIdx.x;
    const int tx = tid & 15, ty = tid >> 4;
    const int r0 = blockIdx.x * 128;

    float acc[8][4];
#pragma unroll
    for (int rr = 0; rr < 8; rr++)
#pragma unroll
        for (int cc = 0; cc < 4; cc++) acc[rr][cc] = 0.f;

    for (int k0 = 0; k0 < KDIM; k0 += 32) {
        // A chunk transposed into k-major: 128 rows x 32 k
#pragma unroll
        for (int i = 0; i < 4; i++) {
            int idx = tid + i * 256;
            int row = idx >> 3, kq = idx & 7;
            float4 v = *(const float4*)&x[(size_t)(r0 + row) * KDIM + k0 + kq * 4];
            As_T[kq * 4 + 0][row] = v.x; As_T[kq * 4 + 1][row] = v.y;
            As_T[kq * 4 + 2][row] = v.z; As_T[kq * 4 + 3][row] = v.w;
        }
        // B chunk: 32 x 64
#pragma unroll
        for (int i = 0; i < 2; i++) {
            int idx = tid + i * 256;
            int kk = idx >> 4, cq = idx & 15;
            *(float4*)&Bs[kk][cq * 4] =
                *(const float4*)&w[(size_t)(k0 + kk) * A3 + cq * 4];
        }
        __syncthreads();
#pragma unroll 8
        for (int k = 0; k < 32; k++) {
            float4 a0 = *(const float4*)&As_T[k][ty * 8];
            float4 a1 = *(const float4*)&As_T[k][ty * 8 + 4];
            float4 bv = *(const float4*)&Bs[k][tx * 4];
            float a[8] = {a0.x, a0.y, a0.z, a0.w, a1.x, a1.y, a1.z, a1.w};
            float b[4] = {bv.x, bv.y, bv.z, bv.w};
#pragma unroll
            for (int rr = 0; rr < 8; rr++)
#pragma unroll
                for (int cc = 0; cc < 4; cc++) acc[rr][cc] += a[rr] * b[cc];
        }
        __syncthreads();
    }
    if (tid < 128) rnorm[tid] = 0.f;
    __syncthreads();
#pragma unroll
    for (int rr = 0; rr < 8; rr++) {
        float p = acc[rr][0] * acc[rr][0] + acc[rr][1] * acc[rr][1]
                + acc[rr][2] * acc[rr][2] + acc[rr][3] * acc[rr][3];
        atomicAdd(&rnorm[ty * 8 + rr], p);
    }
    __syncthreads();
#pragma unroll
    for (int rr = 0; rr < 8; rr++) {
        float s = 1.f / fmaxf(sqrtf(rnorm[ty * 8 + rr]), 1e-12f);
        *(float4*)&g_t[(size_t)(r0 + ty * 8 + rr) * A3 + tx * 4] =
            make_float4(acc[rr][0] * s, acc[rr][1] * s, acc[rr][2] * s, acc[rr][3] * s);
    }
}

// ---------------- K2: windowed FIR sum over C=16 rows ------------------------
__global__ void __launch_bounds__(256) k2_window(const float* __restrict__ lw,
                                                 const float* __restrict__ lb,
                                                 float* __restrict__ rep_out) {
    __shared__ float ts[143 * 64];
    __shared__ float lws[16 * 64];
    __shared__ float sb[64];
    const int tid = threadIdx.x;
    const int r0 = blockIdx.x * 128;
    const int base = (r0 >= 15) ? (r0 - 15) : 0;
    const int nrows = r0 + 128 - base;

    for (int i = tid; i < nrows * 16; i += 256)
        ((float4*)ts)[i] = *(const float4*)&g_t[(size_t)base * A3 + (size_t)i * 4];
    for (int i = tid; i < 256; i += 256)
        ((float4*)lws)[i] = ((const float4*)lw)[i];
    if (tid < 64) {
        float s = 0.f;
#pragma unroll
        for (int j = 0; j < 16; j++) s += lb[j * 64 + tid];
        sb[tid] = s;
    }
    __syncthreads();

    const int c = tid & 63;
    const int rg = tid >> 6;
    float lwr[16];
#pragma unroll
    for (int j = 0; j < 16; j++) lwr[j] = lws[j * 64 + c];
    const float sbc = sb[c];

    for (int rr = 0; rr < 32; rr++) {
        int i = r0 + rg * 32 + rr;
        float accv = sbc;
        if (i >= 15) {
            int off = i - 15 - base;
#pragma unroll
            for (int j = 0; j < 16; j++) accv += lwr[j] * ts[(off + j) * 64 + c];
        } else {
#pragma unroll
            for (int j = 0; j < 16; j++) {
                int s = (j < i) ? j : i;
                accv += lwr[j] * ts[s * 64 + c];
            }
        }
        g_rep[(size_t)i * A3 + c] = accv;
        if (rep_out) rep_out[(size_t)i * A3 + c] = accv;
    }
}

// ---------------- K2t: rep -> rep_T (k-major for k3) + BN accum zeroing ------
__global__ void __launch_bounds__(256) k2t_transpose() {
    __shared__ float tile[32][33];
    const int tx = threadIdx.x & 31, ty = threadIdx.x >> 5;  // 32x8
    const int r0 = blockIdx.x * 32;
    const int c0 = blockIdx.y * 32;
    if (blockIdx.x == 0 && blockIdx.y == 0 && threadIdx.x < 256) {
        int i2 = threadIdx.x;
        g_sum[i2] = 0.f; g_sq[i2] = 0.f;
        g_sum[i2 + 256] = 0.f; g_sq[i2 + 256] = 0.f;
    }
#pragma unroll
    for (int j = 0; j < 32; j += 8)
        tile[ty + j][tx] = g_rep[(size_t)(r0 + ty + j) * A3 + c0 + tx];
    __syncthreads();
#pragma unroll
    for (int j = 0; j < 32; j += 8)
        g_repT[(size_t)(c0 + ty + j) * NROWS + r0 + tx] = tile[tx][ty + j];
}

// ---------------- K3: h[d] = rep @ W1[d] + b1[d]; BN stats -------------------
__global__ void __launch_bounds__(256) k3_tower1(const float* __restrict__ W1,
                                                 const float* __restrict__ b1) {
    __shared__ float As_T[32][132];
    __shared__ float Bs[32][64];
    __shared__ float csum[64];
    __shared__ float csq[64];
    const int tid = threadIdx.x;
    const int tx = tid & 15, ty = tid >> 4;
    const int d = blockIdx.y;
    const int r0 = blockIdx.x * 128;
    if (tid < 64) { csum[tid] = 0.f; csq[tid] = 0.f; }

    float acc[8][4];
#pragma unroll
    for (int rr = 0; rr < 8; rr++)
#pragma unroll
        for (int cc = 0; cc < 4; cc++) acc[rr][cc] = 0.f;

    const float* W1d = W1 + (size_t)d * A3 * A3;
    for (int k0 = 0; k0 < A3; k0 += 32) {
        // A chunk from k-major rep_T: coalesced GMEM, conflict-free STS.128
#pragma unroll
        for (int i = 0; i < 4; i++) {
            int idx = tid + i * 256;
            int kk = idx >> 5, rq = idx & 31;
            *(float4*)&As_T[kk][rq * 4] =
                *(const float4*)&g_repT[(size_t)(k0 + kk) * NROWS + r0 + rq * 4];
        }
#pragma unroll
        for (int i = 0; i < 2; i++) {
            int idx = tid + i * 256;
            int kk = idx >> 4, cq = idx & 15;
            *(float4*)&Bs[kk][cq * 4] =
                *(const float4*)&W1d[(size_t)(k0 + kk) * A3 + cq * 4];
        }
        __syncthreads();
#pragma unroll 8
        for (int k = 0; k < 32; k++) {
            float4 a0 = *(const float4*)&As_T[k][ty * 8];
            float4 a1 = *(const float4*)&As_T[k][ty * 8 + 4];
            float4 bv = *(const float4*)&Bs[k][tx * 4];
            float a[8] = {a0.x, a0.y, a0.z, a0.w, a1.x, a1.y, a1.z, a1.w};
            float b[4] = {bv.x, bv.y, bv.z, bv.w};
#pragma unroll
            for (int rr = 0; rr < 8; rr++)
#pragma unroll
                for (int cc = 0; cc < 4; cc++) acc[rr][cc] += a[rr] * b[cc];
        }
        __syncthreads();
    }
    float4 bv = *(const float4*)&b1[d * A3 + tx * 4];
    float bb[4] = {bv.x, bv.y, bv.z, bv.w};
    float ls[4] = {0, 0, 0, 0}, lq[4] = {0, 0, 0, 0};
#pragma unroll
    for (int rr = 0; rr < 8; rr++) {
        float v0 = acc[rr][0] + bb[0], v1 = acc[rr][1] + bb[1];
        float v2 = acc[rr][2] + bb[2], v3 = acc[rr][3] + bb[3];
        *(float4*)&g_h[((size_t)d * NROWS + r0 + ty * 8 + rr) * A3 + tx * 4] =
            make_float4(v0, v1, v2, v3);
        ls[0] += v0; lq[0] += v0 * v0; ls[1] += v1; lq[1] += v1 * v1;
        ls[2] += v2; lq[2] += v2 * v2; ls[3] += v3; lq[3] += v3 * v3;
    }
#pragma unroll
    for (int cc = 0; cc < 4; cc++) {
        atomicAdd(&csum[tx * 4 + cc], ls[cc]);
        atomicAdd(&csq [tx * 4 + cc], lq[cc]);
    }
    __syncthreads();
    if (tid < 64) {
        atomicAdd(&g_sum[d * A3 + tid], csum[tid]);
        atomicAdd(&g_sq [d * A3 + tid], csq [tid]);
    }
}

// ---------------- K4: finalize BN -> fused scale/shift -----------------------
__global__ void k4_stats(const float* __restrict__ gamma,
                         const float* __restrict__ beta) {
    int i = threadIdx.x;
    if (i < DTOW * A3) {
        const float inv_n = 1.0f / (float)NROWS;
        float mean = g_sum[i] * inv_n;
        float var  = g_sq[i] * inv_n - mean * mean;
        float is   = rsqrtf(var + 1e-5f);
        float sc   = is * gamma[i];
        g_scale[i] = sc;
        g_shift[i] = beta[i] - mean * sc;
    }
}

// ---------------- K5: y[d] = elu(norm(h[d])) @ W2[d] + b2[d] -> g_y ----------
__global__ void __launch_bounds__(256) k5_tower2(const float* __restrict__ W2,
                                                 const float* __restrict__ b2) {
    __shared__ float hs_T[32][132];
    __shared__ float W2s[32][96];
    const int tid = threadIdx.x;
    const int tx = tid & 15, ty = tid >> 4;
    const int d = blockIdx.y;
    const int r0 = blockIdx.x * 128;

    float acc[8][6];
#pragma unroll
    for (int rr = 0; rr < 8; rr++)
#pragma unroll
        for (int cc = 0; cc < 6; cc++) acc[rr][cc] = 0.f;

    const float* W2d = W2 + (size_t)d * A3 * PLEN;
    for (int k0 = 0; k0 < A3; k0 += 32) {
        // h chunk with fused affine + ELU, stored k-major
#pragma unroll
        for (int i = 0; i < 4; i++) {
            int idx = tid + i * 256;
            int row = idx >> 3, kq = idx & 7;
            float4 v  = *(const float4*)&g_h[((size_t)d * NROWS + r0 + row) * A3 + k0 + kq * 4];
            float4 sc = *(const float4*)&g_scale[d * A3 + k0 + kq * 4];
            float4 sh = *(const float4*)&g_shift[d * A3 + k0 + kq * 4];
            float t0 = v.x * sc.x + sh.x; t0 = t0 > 0.f ? t0 : expm1f(t0);
            float t1 = v.y * sc.y + sh.y; t1 = t1 > 0.f ? t1 : expm1f(t1);
            float t2 = v.z * sc.z + sh.z; t2 = t2 > 0.f ? t2 : expm1f(t2);
            float t3 = v.w * sc.w + sh.w; t3 = t3 > 0.f ? t3 : expm1f(t3);
            hs_T[kq * 4 + 0][row] = t0; hs_T[kq * 4 + 1][row] = t1;
            hs_T[kq * 4 + 2][row] = t2; hs_T[kq * 4 + 3][row] = t3;
        }
        // W2 chunk: 32 x 96
#pragma unroll
        for (int i = 0; i < 3; i++) {
            int idx = tid + i * 256;
            int kk = idx / 24, pq = idx % 24;
            *(float4*)&W2s[kk][pq * 4] =
                *(const float4*)&W2d[(size_t)(k0 + kk) * PLEN + pq * 4];
        }
        __syncthreads();
#pragma unroll 8
        for (int k = 0; k < 32; k++) {
            float4 a0 = *(const float4*)&hs_T[k][ty * 8];
            float4 a1 = *(const float4*)&hs_T[k][ty * 8 + 4];
            float2 b0 = *(const float2*)&W2s[k][tx * 6];
            float2 b1v = *(const float2*)&W2s[k][tx * 6 + 2];
            float2 b2v = *(const float2*)&W2s[k][tx * 6 + 4];
            float a[8] = {a0.x, a0.y, a0.z, a0.w, a1.x, a1.y, a1.z, a1.w};
            float b[6] = {b0.x, b0.y, b1v.x, b1v.y, b2v.x, b2v.y};
#pragma unroll
            for (int rr = 0; rr < 8; rr++)
#pragma unroll
                for (int cc = 0; cc < 6; cc++) acc[rr][cc] += a[rr] * b[cc];
        }
        __syncthreads();
    }
    float bb[6];
#pragma unroll
    for (int cc = 0; cc < 6; cc++) bb[cc] = b2[d * PLEN + tx * 6 + cc];
#pragma unroll
    for (int rr = 0; rr < 8; rr++) {
        size_t rowoff = ((size_t)d * NROWS + r0 + ty * 8 + rr) * PLEN;
#pragma unroll
        for (int cc = 0; cc < 6; cc++)
            g_y[rowoff + tx * 6 + cc] = acc[rr][cc] + bb[cc];
    }
}

// ---------------- K6: out[n, p*8+d] = g_y[d][n][p] ---------------------------
__global__ void __launch_bounds__(256) k6_interleave(float* __restrict__ out) {
    const size_t M = (size_t)NROWS * PLEN;
    size_t g = (size_t)blockIdx.x * 256 + threadIdx.x;
    float v[8];
#pragma unroll
    for (int d = 0; d < 8; d++) v[d] = g_y[(size_t)d * M + g];
    float4* o = (float4*)out;
    o[2 * g]     = make_float4(v[0], v[1], v[2], v[3]);
    o[2 * g + 1] = make_float4(v[4], v[5], v[6], v[7]);
}

// ---------------- launch ------------------------------------------------------
extern "C" void kernel_launch(void* const* d_in, const int* in_sizes, int n_in,
                              void* d_out, int out_size) {
    const float* x     = (const float*)d_in[0];
    const float* shu   = (const float*)d_in[1];
    const float* lw    = (const float*)d_in[2];
    const float* lb    = (const float*)d_in[3];
    const float* W1    = (const float*)d_in[4];
    const float* b1    = (const float*)d_in[5];
    const float* gamma = (const float*)d_in[6];
    const float* beta  = (const float*)d_in[7];
    const float* W2    = (const float*)d_in[8];
    const float* b2    = (const float*)d_in[9];
    float* out = (float*)d_out;

    float* rep_out = ((size_t)out_size >= (size_t)NROWS * (PLEN * DTOW + A3))
                         ? out + (size_t)NROWS * PLEN * DTOW
                         : nullptr;

    k1_gemm_norm<<<NROWS / 128, 256>>>(x, shu);
    k2_window<<<NROWS / 128, 256>>>(lw, lb, rep_out);
    k2t_transpose<<<dim3(NROWS / 32, A3 / 32), 256>>>();   // also zeros BN accums
    k3_tower1<<<dim3(NROWS / 128, DTOW), 256>>>(W1, b1);
    k4_stats<<<1, 512>>>(gamma, beta);
    k5_tower2<<<dim3(NROWS / 128, DTOW), 256>>>(W2, b2);
    k6_interleave<<<(NROWS * PLEN) / 256, 256>>>(out);
}